// round 12
// baseline (speedup 1.0000x reference)
#include <cuda_runtime.h>
#include <cstdint>

#define NN      96
#define GRIDN   9216
#define HIDD    9984
#define OUTD    9600
#define BATCH   256
#define INPD    768
#define KDIM    384
#define HPI     1.5707963267948966f

// ---------------------------------------------------------------------------
// hid[:, :9216] = x[:, :384] @ W1[:9216, :384]^T  via mma.sync tf32.
// 512 threads, CTA tile M=128 x N=128, warp tile 64x16 (2x8 warps).
// Staging: PITCH=34 + XOR swizzle of 8-word k-groups (kills STS conflicts).
// ---------------------------------------------------------------------------
#define KC     32
#define NCHK   (KDIM / KC)
#define PITCH  34

__device__ __forceinline__ uint32_t f2tf32(float f) {
    uint32_t o;
    asm("cvt.rna.tf32.f32 %0, %1;" : "=r"(o) : "f"(f));
    return o;
}

__global__ void __launch_bounds__(512)
gemm_tf32_kernel(const float* __restrict__ X, const float* __restrict__ W1,
                 float* __restrict__ hid) {
    __shared__ uint32_t Xs[128 * PITCH];   // 17408 B
    __shared__ uint32_t Ws[128 * PITCH];   // 17408 B

    const int t    = threadIdx.x;
    const int wid  = t >> 5;
    const int lane = t & 31;
    const int g    = lane >> 2;
    const int tg   = lane & 3;
    const int wm   = wid >> 3;             // 0..1 (M: 64 rows)
    const int wn   = wid & 7;              // 0..7 (N: 16 cols)
    const int m0   = blockIdx.y * 128;
    const int n0   = blockIdx.x * 128;

    // Staging: 1024 units over 512 threads -> 2 each. unit = (tile,row,grp).
    const float* srcp[2];
    uint32_t*    dstp[2];
#pragma unroll
    for (int i = 0; i < 2; i++) {
        int idx  = t + i * 512;            // 0..1023
        int tile = idx >> 9;               // 0 = X, 1 = W1
        int rw   = (idx >> 2) & 127;
        int grp  = idx & 3;
        int sgrp = grp ^ (rw & 3);         // swizzled 8-word group
        srcp[i] = (tile ? W1 + (size_t)(n0 + rw) * INPD
                        : X  + (size_t)(m0 + rw) * INPD) + grp * 8;
        dstp[i] = (tile ? Ws : Xs) + rw * PITCH + sgrp * 8;
    }

    float4 lo[2], hi[2];
#pragma unroll
    for (int i = 0; i < 2; i++) {
        lo[i] = *(const float4*)(srcp[i]);
        hi[i] = *(const float4*)(srcp[i] + 4);
    }

    float c[4][2][4];
#pragma unroll
    for (int mf = 0; mf < 4; mf++)
#pragma unroll
        for (int nf = 0; nf < 2; nf++)
#pragma unroll
            for (int q = 0; q < 4; q++) c[mf][nf][q] = 0.0f;

    for (int kc = 0; kc < NCHK; kc++) {
#pragma unroll
        for (int i = 0; i < 2; i++) {
            uint32_t* d = dstp[i];
            d[0] = f2tf32(lo[i].x); d[1] = f2tf32(hi[i].x);
            d[2] = f2tf32(lo[i].y); d[3] = f2tf32(hi[i].y);
            d[4] = f2tf32(lo[i].z); d[5] = f2tf32(hi[i].z);
            d[6] = f2tf32(lo[i].w); d[7] = f2tf32(hi[i].w);
        }
        __syncthreads();

        if (kc + 1 < NCHK) {
            const int off = (kc + 1) * KC;
#pragma unroll
            for (int i = 0; i < 2; i++) {
                lo[i] = *(const float4*)(srcp[i] + off);
                hi[i] = *(const float4*)(srcp[i] + off + 4);
            }
        }

#pragma unroll
        for (int ks = 0; ks < 4; ks++) {
            uint2 a0[4], a1[4], bv[2];
#pragma unroll
            for (int mf = 0; mf < 4; mf++) {
                int r0w = wm * 64 + mf * 16 + g;
                int r1w = r0w + 8;
                a0[mf] = *(const uint2*)&Xs[r0w * PITCH + ((ks ^ (r0w & 3)) << 3) + tg * 2];
                a1[mf] = *(const uint2*)&Xs[r1w * PITCH + ((ks ^ (r1w & 3)) << 3) + tg * 2];
            }
#pragma unroll
            for (int nf = 0; nf < 2; nf++) {
                int cl = wn * 16 + nf * 8 + g;
                bv[nf] = *(const uint2*)&Ws[cl * PITCH + ((ks ^ (cl & 3)) << 3) + tg * 2];
            }
#pragma unroll
            for (int mf = 0; mf < 4; mf++)
#pragma unroll
                for (int nf = 0; nf < 2; nf++)
                    asm volatile(
                        "mma.sync.aligned.m16n8k8.row.col.f32.tf32.tf32.f32 "
                        "{%0,%1,%2,%3}, {%4,%5,%6,%7}, {%8,%9}, {%0,%1,%2,%3};"
                        : "+f"(c[mf][nf][0]), "+f"(c[mf][nf][1]),
                          "+f"(c[mf][nf][2]), "+f"(c[mf][nf][3])
                        : "r"(a0[mf].x), "r"(a1[mf].x), "r"(a0[mf].y), "r"(a1[mf].y),
                          "r"(bv[nf].x), "r"(bv[nf].y));
        }
        __syncthreads();
    }

#pragma unroll
    for (int mf = 0; mf < 4; mf++) {
        int row = m0 + wm * 64 + mf * 16 + g;
#pragma unroll
        for (int nf = 0; nf < 2; nf++) {
            int col = n0 + wn * 16 + nf * 8 + tg * 2;
            float2* q0 = (float2*)(hid + (size_t)row * HIDD + col);
            float2* q1 = (float2*)(hid + (size_t)(row + 8) * HIDD + col);
            *q0 = make_float2(c[mf][nf][0], c[mf][nf][1]);
            *q1 = make_float2(c[mf][nf][2], c[mf][nf][3]);
        }
    }
}

// ---------------------------------------------------------------------------
// Fused spmm, barrier-free (unchanged from R11: measured 15.3us).
// ---------------------------------------------------------------------------
__global__ void __launch_bounds__(256)
spmm_fused_kernel(const float* __restrict__ hid, const float* __restrict__ x,
                  const float* __restrict__ Beta, const float* __restrict__ W2f,
                  float* __restrict__ outp, float* __restrict__ hid_tail_dst) {
    const int t  = threadIdx.x;
    const int by = blockIdx.y;           // 0..7, 32 batches each

    if (blockIdx.x == 150) {             // copy block: x -> hid tail
        for (int i = t; i < 32 * 192; i += 256) {
            int b = by * 32 + (i / 192);
            int q = i % 192;
            const float4* src = (const float4*)(x + (size_t)b * INPD);
            float4*       dst = (float4*)(hid_tail_dst + (size_t)b * HIDD + GRIDN);
            dst[q] = src[q];
        }
        return;
    }

    const int rr = t & 63;
    const int bs = t >> 6;               // 0..3
    const int r  = blockIdx.x * 64 + rr;
    const int bb = by * 32 + bs;

    const float* Br = Beta + (size_t)r * HIDD;
    const float* Fr = W2f  + (size_t)r * HIDD;

    int  c0, c1, c2, c3, c4;
    bool a1f = false, a3f = false;
    bool ghost = (r >= GRIDN);
    if (!ghost) {
        int gi = r / NN, gj = r % NN;
        c0  = r;
        c1  = (gj > 0)      ? r - 1  : GRIDN + 2 * NN + gi;  a1f = (gj == 0);
        c2  = (gj < NN - 1) ? r + 1  : GRIDN + 3 * NN + gi;
        c3  = (gi > 0)      ? r - NN : GRIDN + gj;           a3f = (gi == 0);
        c4  = (gi < NN - 1) ? r + NN : GRIDN + NN + gj;
    } else {
        int gg = r - GRIDN;
        int node;
        if      (gg < NN)     node = gg;
        else if (gg < 2 * NN) node = (NN - 1) * NN + (gg - NN);
        else if (gg < 3 * NN) node = (gg - 2 * NN) * NN;
        else                  node = (gg - 3 * NN) * NN + (NN - 1);
        c0 = r; c1 = node; c2 = OUTD + gg; c3 = 0; c4 = 0;
    }

    float w0 = Fr[c0];
    float w1 = (!ghost && a1f) ? Br[c1] : Fr[c1];
    float w2 = ghost ? Fr[c2] : Br[c2];
    float w3 = ghost ? 0.0f : (a3f ? Br[c3] : Fr[c3]);
    float w4 = ghost ? 0.0f : Br[c4];

    const float* p0; const float* p1; const float* p2; const float* p3; const float* p4;
    int s0, s1, s2, s3, s4;
    p0 = (c0 < GRIDN) ? hid + (size_t)bb * HIDD + c0 : x + (size_t)bb * INPD + (c0 - GRIDN);
    s0 = (c0 < GRIDN) ? 4 * HIDD : 4 * INPD;
    p1 = (c1 < GRIDN) ? hid + (size_t)bb * HIDD + c1 : x + (size_t)bb * INPD + (c1 - GRIDN);
    s1 = (c1 < GRIDN) ? 4 * HIDD : 4 * INPD;
    p2 = (c2 < GRIDN) ? hid + (size_t)bb * HIDD + c2 : x + (size_t)bb * INPD + (c2 - GRIDN);
    s2 = (c2 < GRIDN) ? 4 * HIDD : 4 * INPD;
    p3 = (c3 < GRIDN) ? hid + (size_t)bb * HIDD + c3 : x + (size_t)bb * INPD + (c3 - GRIDN);
    s3 = (c3 < GRIDN) ? 4 * HIDD : 4 * INPD;
    p4 = (c4 < GRIDN) ? hid + (size_t)bb * HIDD + c4 : x + (size_t)bb * INPD + (c4 - GRIDN);
    s4 = (c4 < GRIDN) ? 4 * HIDD : 4 * INPD;

    float v0 = w0;
    float v1 = a1f   ? atanf(w1) + HPI : w1;
    float v2 = ghost ? w2              : atanf(w2) + HPI;
    float v3 = a3f   ? atanf(w3) + HPI : w3;
    float v4 = ghost ? 0.0f            : atanf(w4) + HPI;

    float acc[8];
#pragma unroll
    for (int u = 0; u < 8; u++) acc[u]  = v0 * p0[u * s0];
#pragma unroll
    for (int u = 0; u < 8; u++) acc[u] += v1 * p1[u * s1];
#pragma unroll
    for (int u = 0; u < 8; u++) acc[u] += v2 * p2[u * s2];
#pragma unroll
    for (int u = 0; u < 8; u++) acc[u] += v3 * p3[u * s3];
#pragma unroll
    for (int u = 0; u < 8; u++) acc[u] += v4 * p4[u * s4];

    float* ob = outp + (size_t)bb * OUTD + r;
#pragma unroll
    for (int u = 0; u < 8; u++) ob[(size_t)u * 4 * OUTD] = acc[u];
}

// ---------------------------------------------------------------------------
extern "C" void kernel_launch(void* const* d_in, const int* in_sizes, int n_in,
                              void* d_out, int out_size) {
    const float* x    = (const float*)d_in[0];
    const float* W1   = (const float*)d_in[1];
    const float* Beta = (const float*)d_in[4];
    const float* W2f  = (const float*)d_in[5];

    if (out_size < BATCH * OUTD + BATCH * HIDD) return;   // layout guard

    float* outp = (float*)d_out;                          // [256, 9600]
    float* hid  = (float*)d_out + (size_t)BATCH * OUTD;   // [256, 9984]

    dim3 ggrid(GRIDN / 128, BATCH / 128);   // (72, 2) = 144 blocks, 1/SM
    gemm_tf32_kernel<<<ggrid, 512>>>(x, W1, hid);

    dim3 sgrid(151, 8);                     // 1208 blocks
    spmm_fused_kernel<<<sgrid, 256>>>(hid, x, Beta, W2f, outp, hid);
}

// round 13
// speedup vs baseline: 1.1737x; 1.1737x over previous
#include <cuda_runtime.h>
#include <cstdint>

#define NN      96
#define GRIDN   9216
#define HIDD    9984
#define OUTD    9600
#define BATCH   256
#define INPD    768
#define KDIM    384
#define HPI     1.5707963267948966f

// Static device scratch for sparse W2.
__device__ int   g_cols[OUTD * 5];
__device__ float g_vals[OUTD * 5];

// ---------------------------------------------------------------------------
// Fused: build sparse W2_dyn (blocks 0..37) + copy x -> hid tail (38..101).
// ---------------------------------------------------------------------------
__global__ void __launch_bounds__(256)
prep_kernel(const float* __restrict__ Beta, const float* __restrict__ W2f,
            const float* __restrict__ x, float* __restrict__ hid) {
    const int t = threadIdx.x;
    if (blockIdx.x >= 38) {              // copy: 64 blocks x 4 batches
        int b0 = (blockIdx.x - 38) * 4;
        for (int i = t; i < 4 * 192; i += 256) {
            int b = b0 + (i / 192);
            int q = i % 192;
            const float4* src = (const float4*)(x + (size_t)b * INPD);
            float4*       dst = (float4*)(hid + (size_t)b * HIDD + GRIDN);
            dst[q] = src[q];
        }
        return;
    }
    int r = blockIdx.x * 256 + t;
    if (r >= OUTD) return;
    const float* Br = Beta + (size_t)r * HIDD;
    const float* Fr = W2f  + (size_t)r * HIDD;
    int c[5]; float v[5];
    if (r < GRIDN) {
        int i = r / NN, j = r % NN;
        c[0] = r; v[0] = Fr[r];
        if (j > 0)      { c[1] = r - 1;              v[1] = Fr[c[1]]; }
        else            { c[1] = GRIDN + 2*NN + i;   v[1] = atanf(Br[c[1]]) + HPI; }
        if (j < NN - 1) { c[2] = r + 1;              v[2] = atanf(Br[c[2]]) + HPI; }
        else            { c[2] = GRIDN + 3*NN + i;   v[2] = atanf(Br[c[2]]) + HPI; }
        if (i > 0)      { c[3] = r - NN;             v[3] = Fr[c[3]]; }
        else            { c[3] = GRIDN + j;          v[3] = atanf(Br[c[3]]) + HPI; }
        if (i < NN - 1) { c[4] = r + NN;             v[4] = atanf(Br[c[4]]) + HPI; }
        else            { c[4] = GRIDN + NN + j;     v[4] = atanf(Br[c[4]]) + HPI; }
    } else {
        int g = r - GRIDN;
        int node;
        if      (g < NN)     node = g;
        else if (g < 2 * NN) node = (NN - 1) * NN + (g - NN);
        else if (g < 3 * NN) node = (g - 2 * NN) * NN;
        else                 node = (g - 3 * NN) * NN + (NN - 1);
        c[0] = r;         v[0] = Fr[r];
        c[1] = node;      v[1] = Fr[node];
        c[2] = OUTD + g;  v[2] = Fr[OUTD + g];
        c[3] = 0;         v[3] = 0.0f;
        c[4] = 0;         v[4] = 0.0f;
    }
#pragma unroll
    for (int k = 0; k < 5; k++) {
        g_cols[r * 5 + k] = c[k];
        g_vals[r * 5 + k] = v[k];
    }
}

// ---------------------------------------------------------------------------
// hid[:, :9216] = x[:, :384] @ W1[:9216, :384]^T  via mma.sync tf32.
// CTA tile M=256 (ALL batches) x N=64 -> grid (144,1): W1 read once chip-wide.
// 8 warps as 2(M half) x 4(N); warp tile 128x16; 64 HMMA/warp per k-chunk.
// ---------------------------------------------------------------------------
#define KC     32
#define NCHK   (KDIM / KC)
#define PITCH  40
#define GEMM_SMEM ((256 + 64) * PITCH * 4)   // 51200 B dynamic

__device__ __forceinline__ uint32_t f2tf32(float f) {
    uint32_t o;
    asm("cvt.rna.tf32.f32 %0, %1;" : "=r"(o) : "f"(f));
    return o;
}

__global__ void __launch_bounds__(256)
gemm_tf32_kernel(const float* __restrict__ X, const float* __restrict__ W1,
                 float* __restrict__ hid) {
    extern __shared__ uint32_t sm[];
    uint32_t* Xs = sm;                    // [256][PITCH]
    uint32_t* Ws = sm + 256 * PITCH;      // [64][PITCH]

    const int t    = threadIdx.x;
    const int wid  = t >> 5;
    const int lane = t & 31;
    const int g    = lane >> 2;
    const int tg   = lane & 3;
    const int wm   = wid >> 2;            // 0..1  (M: 128 rows each)
    const int wn   = wid & 3;             // 0..3  (N: 16 cols each)
    const int n0   = blockIdx.x * 64;

    // Staging: 1280 units (X: 1024, W: 256); 5 per thread.
    const float* srcp[5];
    uint32_t*    dstp[5];
#pragma unroll
    for (int i = 0; i < 5; i++) {
        int idx = t + i * 256;            // 0..1279
        if (idx < 1024) {
            int row = idx >> 2, grp = idx & 3;
            srcp[i] = X + (size_t)row * INPD + grp * 8;
            dstp[i] = Xs + row * PITCH + grp * 8;
        } else {
            int w = idx - 1024;
            int row = w >> 2, grp = w & 3;
            srcp[i] = W1 + (size_t)(n0 + row) * INPD + grp * 8;
            dstp[i] = Ws + row * PITCH + grp * 8;
        }
    }

    float4 lo[5], hi[5];
#pragma unroll
    for (int i = 0; i < 5; i++) {
        lo[i] = *(const float4*)(srcp[i]);
        hi[i] = *(const float4*)(srcp[i] + 4);
    }

    float c[8][2][4];
#pragma unroll
    for (int mf = 0; mf < 8; mf++)
#pragma unroll
        for (int nf = 0; nf < 2; nf++)
#pragma unroll
            for (int q = 0; q < 4; q++) c[mf][nf][q] = 0.0f;

    for (int kc = 0; kc < NCHK; kc++) {
#pragma unroll
        for (int i = 0; i < 5; i++) {
            uint32_t* d = dstp[i];
            d[0] = f2tf32(lo[i].x); d[1] = f2tf32(hi[i].x);
            d[2] = f2tf32(lo[i].y); d[3] = f2tf32(hi[i].y);
            d[4] = f2tf32(lo[i].z); d[5] = f2tf32(hi[i].z);
            d[6] = f2tf32(lo[i].w); d[7] = f2tf32(hi[i].w);
        }
        __syncthreads();

        if (kc + 1 < NCHK) {
            const int off = (kc + 1) * KC;
#pragma unroll
            for (int i = 0; i < 5; i++) {
                lo[i] = *(const float4*)(srcp[i] + off);
                hi[i] = *(const float4*)(srcp[i] + off + 4);
            }
        }

#pragma unroll
        for (int ks = 0; ks < 4; ks++) {
            const int kb = ks * 8 + tg * 2;
            uint2 bv[2];
#pragma unroll
            for (int nf = 0; nf < 2; nf++) {
                int col = wn * 16 + nf * 8 + g;
                bv[nf] = *(const uint2*)&Ws[col * PITCH + kb];
            }
#pragma unroll
            for (int mf = 0; mf < 8; mf++) {
                int row = wm * 128 + mf * 16 + g;
                uint2 a0 = *(const uint2*)&Xs[row * PITCH + kb];
                uint2 a1 = *(const uint2*)&Xs[(row + 8) * PITCH + kb];
#pragma unroll
                for (int nf = 0; nf < 2; nf++)
                    asm volatile(
                        "mma.sync.aligned.m16n8k8.row.col.f32.tf32.tf32.f32 "
                        "{%0,%1,%2,%3}, {%4,%5,%6,%7}, {%8,%9}, {%0,%1,%2,%3};"
                        : "+f"(c[mf][nf][0]), "+f"(c[mf][nf][1]),
                          "+f"(c[mf][nf][2]), "+f"(c[mf][nf][3])
                        : "r"(a0.x), "r"(a1.x), "r"(a0.y), "r"(a1.y),
                          "r"(bv[nf].x), "r"(bv[nf].y));
            }
        }
        __syncthreads();
    }

#pragma unroll
    for (int mf = 0; mf < 8; mf++) {
        int row = wm * 128 + mf * 16 + g;
#pragma unroll
        for (int nf = 0; nf < 2; nf++) {
            int col = n0 + wn * 16 + nf * 8 + tg * 2;
            float2* q0 = (float2*)(hid + (size_t)row * HIDD + col);
            float2* q1 = (float2*)(hid + (size_t)(row + 8) * HIDD + col);
            *q0 = make_float2(c[mf][nf][0], c[mf][nf][1]);
            *q1 = make_float2(c[mf][nf][2], c[mf][nf][3]);
        }
    }
}

// ---------------------------------------------------------------------------
// spmm (R7 form — measured 11.6us): 64 rows x 32 batches/block, 8 per thread.
// ---------------------------------------------------------------------------
__global__ void __launch_bounds__(256)
spmm_kernel(const float* __restrict__ hid, float* __restrict__ outp) {
    __shared__ int   sc[64 * 5];
    __shared__ float sv[64 * 5];
    const int r0 = blockIdx.x * 64;
    const int t  = threadIdx.x;
    for (int i = t; i < 320; i += 256) {
        sc[i] = g_cols[r0 * 5 + i];
        sv[i] = g_vals[r0 * 5 + i];
    }
    __syncthreads();
    const int rr = t & 63;
    const int bs = t >> 6;               // 0..3
    const int r  = r0 + rr;
    const int c0 = sc[rr*5+0], c1 = sc[rr*5+1], c2 = sc[rr*5+2],
              c3 = sc[rr*5+3], c4 = sc[rr*5+4];
    const float v0 = sv[rr*5+0], v1 = sv[rr*5+1], v2 = sv[rr*5+2],
                v3 = sv[rr*5+3], v4 = sv[rr*5+4];

    const int bb = blockIdx.y * 32 + bs;
    const float* hb = hid + (size_t)bb * HIDD;
    const size_t ST = (size_t)4 * HIDD;

    float acc[8];
#pragma unroll
    for (int u = 0; u < 8; u++) acc[u]  = v0 * hb[u * ST + c0];
#pragma unroll
    for (int u = 0; u < 8; u++) acc[u] += v1 * hb[u * ST + c1];
#pragma unroll
    for (int u = 0; u < 8; u++) acc[u] += v2 * hb[u * ST + c2];
#pragma unroll
    for (int u = 0; u < 8; u++) acc[u] += v3 * hb[u * ST + c3];
#pragma unroll
    for (int u = 0; u < 8; u++) acc[u] += v4 * hb[u * ST + c4];

    float* ob = outp + (size_t)bb * OUTD + r;
#pragma unroll
    for (int u = 0; u < 8; u++) ob[u * 4 * OUTD] = acc[u];
}

// ---------------------------------------------------------------------------
extern "C" void kernel_launch(void* const* d_in, const int* in_sizes, int n_in,
                              void* d_out, int out_size) {
    const float* x    = (const float*)d_in[0];
    const float* W1   = (const float*)d_in[1];
    const float* Beta = (const float*)d_in[4];
    const float* W2f  = (const float*)d_in[5];

    if (out_size < BATCH * OUTD + BATCH * HIDD) return;   // layout guard

    float* outp = (float*)d_out;                          // [256, 9600]
    float* hid  = (float*)d_out + (size_t)BATCH * OUTD;   // [256, 9984]

    // build W2 values + tail copy (independent of GEMM)
    prep_kernel<<<102, 256>>>(Beta, W2f, x, hid);

    cudaFuncSetAttribute(gemm_tf32_kernel,
                         cudaFuncAttributeMaxDynamicSharedMemorySize, GEMM_SMEM);
    gemm_tf32_kernel<<<144, 256, GEMM_SMEM>>>(x, W1, hid);

    dim3 sgrid(OUTD / 64, 8);             // (150, 8)
    spmm_kernel<<<sgrid, 256>>>(hid, outp);
}

// round 14
// speedup vs baseline: 1.4314x; 1.2195x over previous
#include <cuda_runtime.h>
#include <cstdint>

#define NN      96
#define GRIDN   9216
#define HIDD    9984
#define OUTD    9600
#define BATCH   256
#define INPD    768
#define KDIM    384
#define HPI     1.5707963267948966f

// Static device scratch for sparse W2.
__device__ int   g_cols[OUTD * 5];
__device__ float g_vals[OUTD * 5];

#define KC     32
#define NCHK   (KDIM / KC)
#define PITCH  40

__device__ __forceinline__ uint32_t f2tf32(float f) {
    uint32_t o;
    asm("cvt.rna.tf32.f32 %0, %1;" : "=r"(o) : "f"(f));
    return o;
}

// ---------------------------------------------------------------------------
// Mega kernel, grid 246:
//   blocks   0..143 : tf32 GEMM, hid[:, :9216] = x[:,:384] @ W1[:9216,:384]^T
//                     (R7 form: 128x128 tile, reg double-buffer, LDS.64)
//   blocks 144..181 : build sparse W2_dyn -> g_cols/g_vals
//   blocks 182..245 : copy x -> hid[:, 9216:9984]
// All three roles are mutually independent; prep latency hides under GEMM.
// ---------------------------------------------------------------------------
__global__ void __launch_bounds__(256)
mega_kernel(const float* __restrict__ X, const float* __restrict__ W1,
            const float* __restrict__ Beta, const float* __restrict__ W2f,
            float* __restrict__ hid) {
    __shared__ uint32_t Xs[128 * PITCH];
    __shared__ uint32_t Ws[128 * PITCH];

    const int b = blockIdx.x;
    const int t = threadIdx.x;

    if (b >= 144) {
        if (b >= 182) {                  // ---- copy role: 4 batches/block
            int b0 = (b - 182) * 4;
            for (int i = t; i < 4 * 192; i += 256) {
                int bb = b0 + (i / 192);
                int q  = i % 192;
                const float4* src = (const float4*)(X + (size_t)bb * INPD);
                float4*       dst = (float4*)(hid + (size_t)bb * HIDD + GRIDN);
                dst[q] = src[q];
            }
            return;
        }
        // ---- build role: one row per thread
        int r = (b - 144) * 256 + t;
        if (r >= OUTD) return;
        const float* Br = Beta + (size_t)r * HIDD;
        const float* Fr = W2f  + (size_t)r * HIDD;
        int c[5]; float v[5];
        if (r < GRIDN) {
            int i = r / NN, j = r % NN;
            c[0] = r; v[0] = Fr[r];
            if (j > 0)      { c[1] = r - 1;              v[1] = Fr[c[1]]; }
            else            { c[1] = GRIDN + 2*NN + i;   v[1] = atanf(Br[c[1]]) + HPI; }
            if (j < NN - 1) { c[2] = r + 1;              v[2] = atanf(Br[c[2]]) + HPI; }
            else            { c[2] = GRIDN + 3*NN + i;   v[2] = atanf(Br[c[2]]) + HPI; }
            if (i > 0)      { c[3] = r - NN;             v[3] = Fr[c[3]]; }
            else            { c[3] = GRIDN + j;          v[3] = atanf(Br[c[3]]) + HPI; }
            if (i < NN - 1) { c[4] = r + NN;             v[4] = atanf(Br[c[4]]) + HPI; }
            else            { c[4] = GRIDN + NN + j;     v[4] = atanf(Br[c[4]]) + HPI; }
        } else {
            int g = r - GRIDN;
            int node;
            if      (g < NN)     node = g;
            else if (g < 2 * NN) node = (NN - 1) * NN + (g - NN);
            else if (g < 3 * NN) node = (g - 2 * NN) * NN;
            else                 node = (g - 3 * NN) * NN + (NN - 1);
            c[0] = r;         v[0] = Fr[r];
            c[1] = node;      v[1] = Fr[node];
            c[2] = OUTD + g;  v[2] = Fr[OUTD + g];
            c[3] = 0;         v[3] = 0.0f;
            c[4] = 0;         v[4] = 0.0f;
        }
#pragma unroll
        for (int k = 0; k < 5; k++) {
            g_cols[r * 5 + k] = c[k];
            g_vals[r * 5 + k] = v[k];
        }
        return;
    }

    // ---- GEMM role ----
    const int wid  = t >> 5;
    const int lane = t & 31;
    const int g    = lane >> 2;
    const int tg   = lane & 3;
    const int wm   = wid >> 2;
    const int wn   = wid & 3;
    const int m0   = (b / 72) * 128;
    const int n0   = (b % 72) * 128;

    const float* srcp[4];
    uint32_t*    dstp[4];
#pragma unroll
    for (int i = 0; i < 4; i++) {
        int idx  = t + i * 256;
        int tile = idx >> 9;
        int row  = (idx >> 2) & 127;
        int grp  = idx & 3;
        srcp[i] = (tile ? W1 + (size_t)(n0 + row) * INPD
                        : X  + (size_t)(m0 + row) * INPD) + grp * 8;
        dstp[i] = (tile ? Ws : Xs) + row * PITCH + grp * 8;
    }

    float4 lo[4], hi[4];
#pragma unroll
    for (int i = 0; i < 4; i++) {
        lo[i] = *(const float4*)(srcp[i]);
        hi[i] = *(const float4*)(srcp[i] + 4);
    }

    float c[4][4][4];
#pragma unroll
    for (int mf = 0; mf < 4; mf++)
#pragma unroll
        for (int nf = 0; nf < 4; nf++)
#pragma unroll
            for (int q = 0; q < 4; q++) c[mf][nf][q] = 0.0f;

    for (int kc = 0; kc < NCHK; kc++) {
#pragma unroll
        for (int i = 0; i < 4; i++) {
            uint32_t* d = dstp[i];
            d[0] = f2tf32(lo[i].x); d[1] = f2tf32(hi[i].x);
            d[2] = f2tf32(lo[i].y); d[3] = f2tf32(hi[i].y);
            d[4] = f2tf32(lo[i].z); d[5] = f2tf32(hi[i].z);
            d[6] = f2tf32(lo[i].w); d[7] = f2tf32(hi[i].w);
        }
        __syncthreads();

        if (kc + 1 < NCHK) {
            const int off = (kc + 1) * KC;
#pragma unroll
            for (int i = 0; i < 4; i++) {
                lo[i] = *(const float4*)(srcp[i] + off);
                hi[i] = *(const float4*)(srcp[i] + off + 4);
            }
        }

#pragma unroll
        for (int ks = 0; ks < 4; ks++) {
            const int kb = ks * 8 + tg * 2;
            uint2 a0[4], a1[4], bv[4];
#pragma unroll
            for (int mf = 0; mf < 4; mf++) {
                int row = wm * 64 + mf * 16 + g;
                a0[mf] = *(const uint2*)&Xs[row * PITCH + kb];
                a1[mf] = *(const uint2*)&Xs[(row + 8) * PITCH + kb];
            }
#pragma unroll
            for (int nf = 0; nf < 4; nf++) {
                int col = wn * 32 + nf * 8 + g;
                bv[nf] = *(const uint2*)&Ws[col * PITCH + kb];
            }
#pragma unroll
            for (int mf = 0; mf < 4; mf++)
#pragma unroll
                for (int nf = 0; nf < 4; nf++)
                    asm volatile(
                        "mma.sync.aligned.m16n8k8.row.col.f32.tf32.tf32.f32 "
                        "{%0,%1,%2,%3}, {%4,%5,%6,%7}, {%8,%9}, {%0,%1,%2,%3};"
                        : "+f"(c[mf][nf][0]), "+f"(c[mf][nf][1]),
                          "+f"(c[mf][nf][2]), "+f"(c[mf][nf][3])
                        : "r"(a0[mf].x), "r"(a1[mf].x), "r"(a0[mf].y), "r"(a1[mf].y),
                          "r"(bv[nf].x), "r"(bv[nf].y));
        }
        __syncthreads();
    }

#pragma unroll
    for (int mf = 0; mf < 4; mf++) {
        int row = m0 + wm * 64 + mf * 16 + g;
#pragma unroll
        for (int nf = 0; nf < 4; nf++) {
            int col = n0 + wn * 32 + nf * 8 + tg * 2;
            float2* p0 = (float2*)(hid + (size_t)row * HIDD + col);
            float2* p1 = (float2*)(hid + (size_t)(row + 8) * HIDD + col);
            *p0 = make_float2(c[mf][nf][0], c[mf][nf][1]);
            *p1 = make_float2(c[mf][nf][2], c[mf][nf][3]);
        }
    }
}

// ---------------------------------------------------------------------------
// spmm (R7 measured-best form): 64 rows x 32 batches/block, 8 per thread.
// ---------------------------------------------------------------------------
__global__ void __launch_bounds__(256)
spmm_kernel(const float* __restrict__ hid, float* __restrict__ outp) {
    __shared__ int   sc[64 * 5];
    __shared__ float sv[64 * 5];
    const int r0 = blockIdx.x * 64;
    const int t  = threadIdx.x;
    for (int i = t; i < 320; i += 256) {
        sc[i] = g_cols[r0 * 5 + i];
        sv[i] = g_vals[r0 * 5 + i];
    }
    __syncthreads();
    const int rr = t & 63;
    const int bs = t >> 6;
    const int r  = r0 + rr;
    const int c0 = sc[rr*5+0], c1 = sc[rr*5+1], c2 = sc[rr*5+2],
              c3 = sc[rr*5+3], c4 = sc[rr*5+4];
    const float v0 = sv[rr*5+0], v1 = sv[rr*5+1], v2 = sv[rr*5+2],
                v3 = sv[rr*5+3], v4 = sv[rr*5+4];

    const int bb = blockIdx.y * 32 + bs;
    const float* hb = hid + (size_t)bb * HIDD;
    const size_t ST = (size_t)4 * HIDD;

    float acc[8];
#pragma unroll
    for (int u = 0; u < 8; u++) acc[u]  = v0 * hb[u * ST + c0];
#pragma unroll
    for (int u = 0; u < 8; u++) acc[u] += v1 * hb[u * ST + c1];
#pragma unroll
    for (int u = 0; u < 8; u++) acc[u] += v2 * hb[u * ST + c2];
#pragma unroll
    for (int u = 0; u < 8; u++) acc[u] += v3 * hb[u * ST + c3];
#pragma unroll
    for (int u = 0; u < 8; u++) acc[u] += v4 * hb[u * ST + c4];

    float* ob = outp + (size_t)bb * OUTD + r;
#pragma unroll
    for (int u = 0; u < 8; u++) ob[u * 4 * OUTD] = acc[u];
}

// ---------------------------------------------------------------------------
extern "C" void kernel_launch(void* const* d_in, const int* in_sizes, int n_in,
                              void* d_out, int out_size) {
    const float* x    = (const float*)d_in[0];
    const float* W1   = (const float*)d_in[1];
    const float* Beta = (const float*)d_in[4];
    const float* W2f  = (const float*)d_in[5];

    if (out_size < BATCH * OUTD + BATCH * HIDD) return;   // layout guard

    float* outp = (float*)d_out;                          // [256, 9600]
    float* hid  = (float*)d_out + (size_t)BATCH * OUTD;   // [256, 9984]

    mega_kernel<<<246, 256>>>(x, W1, Beta, W2f, hid);

    dim3 sgrid(OUTD / 64, 8);             // (150, 8)
    spmm_kernel<<<sgrid, 256>>>(hid, outp);
}